// round 1
// baseline (speedup 1.0000x reference)
#include <cuda_runtime.h>
#include <cstddef>

#define AZf (-999999.0f)

static const int NMAX = 100000;

// Scratch: hidden activations (no cudaMalloc allowed -> device globals)
__device__ float g_h1[(size_t)NMAX * 256];
__device__ float g_h2[(size_t)NMAX * 256];

// ---------------------------------------------------------------------------
// Classic 128x128x8 SGEMM, 256 threads, 8x8 microtile (4+4 quadrant split).
// C[M,N] = act(A[M,K] @ B[K,N] + bias), row-major everything.
// N must be a multiple of 128 (it is: 256). M guarded.
// ---------------------------------------------------------------------------
template<bool RELU>
__global__ __launch_bounds__(256) void sgemm_bias(
    const float* __restrict__ A, const float* __restrict__ B,
    const float* __restrict__ bias, float* __restrict__ C,
    int M, int N, int K)
{
    __shared__ float As[8][128];
    __shared__ float Bs[8][128];
    const int tid  = threadIdx.x;
    const int tx   = tid & 15;          // 0..15 col group
    const int ty   = tid >> 4;          // 0..15 row group
    const int aRow = tid >> 1;          // 0..127
    const int aCol = (tid & 1) << 2;    // 0 or 4
    const int bRow = tid >> 5;          // 0..7
    const int bCol = (tid & 31) << 2;   // 0..124
    const int mBase = blockIdx.y * 128;
    const int nBase = blockIdx.x * 128;
    const bool aValid = (mBase + aRow) < M;
    const float* Aptr = A + (size_t)(mBase + aRow) * K;
    const float* Bptr = B + nBase;

    float acc[8][8];
#pragma unroll
    for (int i = 0; i < 8; i++)
#pragma unroll
        for (int j = 0; j < 8; j++) acc[i][j] = 0.f;

    for (int k0 = 0; k0 < K; k0 += 8) {
        float4 av = make_float4(0.f, 0.f, 0.f, 0.f);
        if (aValid) av = *reinterpret_cast<const float4*>(Aptr + k0 + aCol);
        As[aCol + 0][aRow] = av.x;
        As[aCol + 1][aRow] = av.y;
        As[aCol + 2][aRow] = av.z;
        As[aCol + 3][aRow] = av.w;
        *reinterpret_cast<float4*>(&Bs[bRow][bCol]) =
            *reinterpret_cast<const float4*>(Bptr + (size_t)(k0 + bRow) * N + bCol);
        __syncthreads();
#pragma unroll
        for (int k = 0; k < 8; k++) {
            float a[8], b[8];
            float4 t;
            t = *reinterpret_cast<const float4*>(&As[k][ty * 4]);
            a[0] = t.x; a[1] = t.y; a[2] = t.z; a[3] = t.w;
            t = *reinterpret_cast<const float4*>(&As[k][64 + ty * 4]);
            a[4] = t.x; a[5] = t.y; a[6] = t.z; a[7] = t.w;
            t = *reinterpret_cast<const float4*>(&Bs[k][tx * 4]);
            b[0] = t.x; b[1] = t.y; b[2] = t.z; b[3] = t.w;
            t = *reinterpret_cast<const float4*>(&Bs[k][64 + tx * 4]);
            b[4] = t.x; b[5] = t.y; b[6] = t.z; b[7] = t.w;
#pragma unroll
            for (int i = 0; i < 8; i++)
#pragma unroll
                for (int j = 0; j < 8; j++) acc[i][j] += a[i] * b[j];
        }
        __syncthreads();
    }

#pragma unroll
    for (int ii = 0; ii < 8; ii++) {
        int row = mBase + ((ii < 4) ? (ty * 4 + ii) : (64 + ty * 4 + ii - 4));
        if (row >= M) continue;
#pragma unroll
        for (int jg = 0; jg < 2; jg++) {
            int colBase = nBase + jg * 64 + tx * 4;
            float4 v;
            float* vp = &v.x;
#pragma unroll
            for (int j = 0; j < 4; j++) {
                float x = acc[ii][jg * 4 + j] + bias[colBase + j];
                if (RELU) x = fmaxf(x, 0.f);
                vp[j] = x;
            }
            *reinterpret_cast<float4*>(C + (size_t)row * N + colBase) = v;
        }
    }
}

// ---------------------------------------------------------------------------
// Edge GEMM: A rows are gathered [h2[parent[e]] | h2[child[e]]] (K=512),
// B = We [512,256], epilogue applies CRF observation masking and writes
// ep_masked[e, r, c] at out[e*256 + r*16 + c].
// ---------------------------------------------------------------------------
__global__ __launch_bounds__(256) void edge_gemm(
    const float* __restrict__ h, const float* __restrict__ We,
    const float* __restrict__ be,
    const int* __restrict__ parent, const int* __restrict__ child,
    const int* __restrict__ obs, const int* __restrict__ tl,
    float* __restrict__ out, int E)
{
    __shared__ float As[8][128];
    __shared__ float Bs[8][128];
    const int tid  = threadIdx.x;
    const int tx   = tid & 15;
    const int ty   = tid >> 4;
    const int aRow = tid >> 1;
    const int aCol = (tid & 1) << 2;
    const int bRow = tid >> 5;
    const int bCol = (tid & 31) << 2;
    const int mBase = blockIdx.y * 128;
    const int nBase = blockIdx.x * 128;   // 0 or 128
    const int eA = mBase + aRow;
    const bool aValid = eA < E;
    const float* rowP = h;
    const float* rowC = h;
    if (aValid) {
        rowP = h + (size_t)parent[eA] * 256;
        rowC = h + (size_t)child[eA]  * 256;
    }
    const float* Bptr = We + nBase;

    float acc[8][8];
#pragma unroll
    for (int i = 0; i < 8; i++)
#pragma unroll
        for (int j = 0; j < 8; j++) acc[i][j] = 0.f;

    for (int k0 = 0; k0 < 512; k0 += 8) {
        int k = k0 + aCol;
        float4 av = make_float4(0.f, 0.f, 0.f, 0.f);
        if (aValid) {
            const float* p = (k < 256) ? (rowP + k) : (rowC + (k - 256));
            av = *reinterpret_cast<const float4*>(p);
        }
        As[aCol + 0][aRow] = av.x;
        As[aCol + 1][aRow] = av.y;
        As[aCol + 2][aRow] = av.z;
        As[aCol + 3][aRow] = av.w;
        *reinterpret_cast<float4*>(&Bs[bRow][bCol]) =
            *reinterpret_cast<const float4*>(Bptr + (size_t)(k0 + bRow) * 256 + bCol);
        __syncthreads();
#pragma unroll
        for (int kk = 0; kk < 8; kk++) {
            float a[8], b[8];
            float4 t;
            t = *reinterpret_cast<const float4*>(&As[kk][ty * 4]);
            a[0] = t.x; a[1] = t.y; a[2] = t.z; a[3] = t.w;
            t = *reinterpret_cast<const float4*>(&As[kk][64 + ty * 4]);
            a[4] = t.x; a[5] = t.y; a[6] = t.z; a[7] = t.w;
            t = *reinterpret_cast<const float4*>(&Bs[kk][tx * 4]);
            b[0] = t.x; b[1] = t.y; b[2] = t.z; b[3] = t.w;
            t = *reinterpret_cast<const float4*>(&Bs[kk][64 + tx * 4]);
            b[4] = t.x; b[5] = t.y; b[6] = t.z; b[7] = t.w;
#pragma unroll
            for (int i = 0; i < 8; i++)
#pragma unroll
                for (int j = 0; j < 8; j++) acc[i][j] += a[i] * b[j];
        }
        __syncthreads();
    }

#pragma unroll
    for (int ii = 0; ii < 8; ii++) {
        int e = mBase + ((ii < 4) ? (ty * 4 + ii) : (64 + ty * 4 + ii - 4));
        if (e >= E) continue;
        const int pi = parent[e];
        const int ci = child[e];
        const int pl = tl[pi];
        const int cl = tl[ci];
        const int op = obs[pi];
        const int oc = obs[ci];
#pragma unroll
        for (int jg = 0; jg < 2; jg++) {
            int colBase = nBase + jg * 64 + tx * 4;
            float4 v;
            float* vp = &v.x;
#pragma unroll
            for (int j = 0; j < 4; j++) {
                int col = colBase + j;
                int r = col >> 4;
                int c = col & 15;
                float ep = acc[ii][jg * 4 + j] + be[col];
                float x;
                if (op && oc)      x = (r == pl && c == cl) ? 0.f : AZf;
                else if (oc)       x = ep + ((r == cl) ? 0.f : AZf);
                else if (op)       x = ep + ((c == pl) ? 0.f : AZf);
                else               x = ep;
                vp[j] = x;
            }
            *reinterpret_cast<float4*>(out + (size_t)e * 256 + colBase) = v;
        }
    }
}

// ---------------------------------------------------------------------------
// Unary: out[row, c] = obs ? (tl==c ? 0 : AZ) : h2[row]·Wu[:,c] + bu[c]
// One block = 16 rows x 16 cols.
// ---------------------------------------------------------------------------
__global__ __launch_bounds__(256) void unary_kernel(
    const float* __restrict__ h, const float* __restrict__ Wu,
    const float* __restrict__ bu, const int* __restrict__ obs,
    const int* __restrict__ tl, float* __restrict__ out, int N)
{
    __shared__ float sW[256 * 16];
    __shared__ float sH[16][257];
    const int tid = threadIdx.x;
    for (int i = tid; i < 256 * 16; i += 256) sW[i] = Wu[i];
    const int row0 = blockIdx.x * 16;
    const int limit = (N - row0 < 16 ? N - row0 : 16) * 256;
    for (int i = tid; i < 16 * 256; i += 256)
        sH[i >> 8][i & 255] = (i < limit) ? h[(size_t)row0 * 256 + i] : 0.f;
    __syncthreads();
    const int tx = tid & 15, ty = tid >> 4;
    const int row = row0 + ty;
    if (row >= N) return;
    float acc = 0.f;
#pragma unroll 8
    for (int k = 0; k < 256; k++) acc += sH[ty][k] * sW[k * 16 + tx];
    float v;
    if (obs[row]) v = (tl[row] == tx) ? 0.f : AZf;
    else          v = acc + bu[tx];
    out[(size_t)row * 16 + tx] = v;
}

// ---------------------------------------------------------------------------

extern "C" void kernel_launch(void* const* d_in, const int* in_sizes, int n_in,
                              void* d_out, int out_size)
{
    const float* features = (const float*)d_in[0];
    const int*   parent   = (const int*)  d_in[1];
    const int*   child    = (const int*)  d_in[2];
    const int*   obs      = (const int*)  d_in[3];
    const int*   tl       = (const int*)  d_in[4];
    const float* W1       = (const float*)d_in[5];
    const float* b1       = (const float*)d_in[6];
    const float* W2       = (const float*)d_in[7];
    const float* b2       = (const float*)d_in[8];
    const float* Wu       = (const float*)d_in[9];
    const float* bu       = (const float*)d_in[10];
    const float* We       = (const float*)d_in[11];
    const float* be       = (const float*)d_in[12];

    const int N = in_sizes[0] / 768;
    const int E = in_sizes[1];

    float* out  = (float*)d_out;
    float* outU = out;
    float* outE = out + (size_t)N * 16;

    float *h1, *h2;
    cudaGetSymbolAddress((void**)&h1, g_h1);
    cudaGetSymbolAddress((void**)&h2, g_h2);

    dim3 blk(256);
    dim3 gN(2, (N + 127) / 128);
    dim3 gE(2, (E + 127) / 128);

    sgemm_bias<true><<<gN, blk>>>(features, W1, b1, h1, N, 256, 768);
    sgemm_bias<true><<<gN, blk>>>(h1,       W2, b2, h2, N, 256, 256);
    unary_kernel<<<(N + 15) / 16, blk>>>(h2, Wu, bu, obs, tl, outU, N);
    edge_gemm<<<gE, blk>>>(h2, We, be, parent, child, obs, tl, outE, E);
}

// round 3
// speedup vs baseline: 3.1978x; 3.1978x over previous
#include <cuda_runtime.h>
#include <cuda_bf16.h>
#include <cstdint>
#include <cstddef>

#define AZf (-999999.0f)
static const int NMAXC = 100000;

// Scratch (no cudaMalloc allowed)
__device__ __nv_bfloat16 g_h1[(size_t)NMAXC * 256];
__device__ __nv_bfloat16 g_h2[(size_t)NMAXC * 256];
__device__ __nv_bfloat16 g_Wt1[256 * 768];
__device__ __nv_bfloat16 g_Wt2[256 * 256];
__device__ __nv_bfloat16 g_Wet[256 * 512];

// ---------------- helpers ----------------
__device__ __forceinline__ uint32_t smem_u32(const void* p) {
    uint32_t a;
    asm("{ .reg .u64 t; cvta.to.shared.u64 t, %1; cvt.u32.u64 %0, t; }" : "=r"(a) : "l"(p));
    return a;
}
__device__ __forceinline__ void ldsm4(uint32_t& r0, uint32_t& r1, uint32_t& r2, uint32_t& r3, uint32_t addr) {
    asm volatile("ldmatrix.sync.aligned.m8n8.x4.shared.b16 {%0,%1,%2,%3}, [%4];"
                 : "=r"(r0), "=r"(r1), "=r"(r2), "=r"(r3) : "r"(addr));
}
__device__ __forceinline__ void mma_bf16(float* c, const uint32_t* a, uint32_t b0, uint32_t b1) {
    asm volatile("mma.sync.aligned.m16n8k16.row.col.f32.bf16.bf16.f32 "
                 "{%0,%1,%2,%3}, {%4,%5,%6,%7}, {%8,%9}, {%0,%1,%2,%3};"
                 : "+f"(c[0]), "+f"(c[1]), "+f"(c[2]), "+f"(c[3])
                 : "r"(a[0]), "r"(a[1]), "r"(a[2]), "r"(a[3]), "r"(b0), "r"(b1));
}
__device__ __forceinline__ uint32_t pack_bf16(float lo, float hi) {
    __nv_bfloat162 h = __floats2bfloat162_rn(lo, hi);
    return *reinterpret_cast<uint32_t*>(&h);
}

// SMEM: rows of 32 bf16 (64B payload) at 80B stride -> conflict-free ldmatrix
static constexpr int RSTR = 80;
static constexpr uint32_t A0_OFF = 0;          // 128 rows
static constexpr uint32_t A1_OFF = 10240;
static constexpr uint32_t B0_OFF = 20480;      // 128 rows
static constexpr uint32_t B1_OFF = 30720;
static constexpr int SMEM_BYTES = 40960;

// ---------------------------------------------------------------------------
// Transpose + fp32->bf16: Wt[n][k] = bf16(W[k][n])
// ---------------------------------------------------------------------------
__global__ void transpose_w(const float* __restrict__ W, __nv_bfloat16* __restrict__ Wt, int K, int N) {
    __shared__ float t[32][33];
    int k0 = blockIdx.y * 32, n0 = blockIdx.x * 32;
    int x = threadIdx.x, y = threadIdx.y;
#pragma unroll
    for (int i = 0; i < 32; i += 8) {
        int k = k0 + y + i, n = n0 + x;
        t[y + i][x] = (k < K && n < N) ? W[(size_t)k * N + n] : 0.f;
    }
    __syncthreads();
#pragma unroll
    for (int i = 0; i < 32; i += 8) {
        int n = n0 + y + i, k = k0 + x;
        if (n < N && k < K) Wt[(size_t)n * K + k] = __float2bfloat16(t[x][y + i]);
    }
}

// ---------------------------------------------------------------------------
// bf16 tensor-core GEMM: C[M,256] = bf16(relu(A[M,K] @ Bt[256,K]^T + bias))
// A fp32 (A_BF16=false) or bf16. 128x128 tile, 8 warps (4x2), K-chunk 32.
// ---------------------------------------------------------------------------
template<bool A_BF16>
__global__ __launch_bounds__(256) void hgemm_relu(
    const void* __restrict__ Av, const __nv_bfloat16* __restrict__ Bt,
    const float* __restrict__ bias, __nv_bfloat16* __restrict__ C,
    int M, int K)
{
    extern __shared__ uint8_t smem[];
    const uint32_t sbase = smem_u32(smem);
    const int tid = threadIdx.x, lane = tid & 31, wid = tid >> 5;
    const int mBase = blockIdx.y << 7, nBase = blockIdx.x << 7;
    const int warp_m = (wid & 3) << 5, warp_n = (wid >> 2) << 6;

    const int lr = tid >> 1;            // 0..127
    const int kh = (tid & 1) << 4;      // 0 or 16
    const bool mv = (mBase + lr) < M;
    const float* Af = (const float*)Av;
    const __nv_bfloat16* Ab = (const __nv_bfloat16*)Av;
    const __nv_bfloat16* bRow = Bt + (size_t)(nBase + lr) * K + kh;

    float acc[2][8][4];
#pragma unroll
    for (int i = 0; i < 2; i++)
#pragma unroll
        for (int j = 0; j < 8; j++)
#pragma unroll
            for (int l = 0; l < 4; l++) acc[i][j][l] = 0.f;

    uint32_t aR[8], bR[8];

    auto ldgA = [&](int c) {
        const int k0 = c * 32 + kh;
        if (!mv) {
#pragma unroll
            for (int i = 0; i < 8; i++) aR[i] = 0;
        } else if (A_BF16) {
            const uint4* p = (const uint4*)(Ab + (size_t)(mBase + lr) * K + k0);
            uint4 v0 = p[0], v1 = p[1];
            aR[0] = v0.x; aR[1] = v0.y; aR[2] = v0.z; aR[3] = v0.w;
            aR[4] = v1.x; aR[5] = v1.y; aR[6] = v1.z; aR[7] = v1.w;
        } else {
            const float4* p = (const float4*)(Af + (size_t)(mBase + lr) * K + k0);
            float4 f0 = p[0], f1 = p[1], f2 = p[2], f3 = p[3];
            aR[0] = pack_bf16(f0.x, f0.y); aR[1] = pack_bf16(f0.z, f0.w);
            aR[2] = pack_bf16(f1.x, f1.y); aR[3] = pack_bf16(f1.z, f1.w);
            aR[4] = pack_bf16(f2.x, f2.y); aR[5] = pack_bf16(f2.z, f2.w);
            aR[6] = pack_bf16(f3.x, f3.y); aR[7] = pack_bf16(f3.z, f3.w);
        }
    };
    auto ldgB = [&](int c) {
        const uint4* p = (const uint4*)(bRow + c * 32);
        uint4 v0 = p[0], v1 = p[1];
        bR[0] = v0.x; bR[1] = v0.y; bR[2] = v0.z; bR[3] = v0.w;
        bR[4] = v1.x; bR[5] = v1.y; bR[6] = v1.z; bR[7] = v1.w;
    };
    auto sts = [&](uint32_t aOff, uint32_t bOff) {
        uint8_t* sa = smem + aOff + lr * RSTR + kh * 2;
        *(uint4*)(sa)      = make_uint4(aR[0], aR[1], aR[2], aR[3]);
        *(uint4*)(sa + 16) = make_uint4(aR[4], aR[5], aR[6], aR[7]);
        uint8_t* sb = smem + bOff + lr * RSTR + kh * 2;
        *(uint4*)(sb)      = make_uint4(bR[0], bR[1], bR[2], bR[3]);
        *(uint4*)(sb + 16) = make_uint4(bR[4], bR[5], bR[6], bR[7]);
    };
    auto compute = [&](uint32_t aOff, uint32_t bOff) {
        const uint32_t aBase = sbase + aOff + (warp_m + (lane & 15)) * RSTR + ((lane >> 4) << 4);
        const uint32_t bBase = sbase + bOff + ((lane & 7) + ((lane >> 4) << 3)) * RSTR + (((lane >> 3) & 1) << 4);
#pragma unroll
        for (int ks = 0; ks < 2; ks++) {
            uint32_t a[2][4];
            ldsm4(a[0][0], a[0][1], a[0][2], a[0][3], aBase + ks * 32);
            ldsm4(a[1][0], a[1][1], a[1][2], a[1][3], aBase + 16 * RSTR + ks * 32);
            uint32_t b[4][4];
#pragma unroll
            for (int np = 0; np < 4; np++)
                ldsm4(b[np][0], b[np][1], b[np][2], b[np][3], bBase + np * 16 * RSTR + ks * 32);
#pragma unroll
            for (int mt = 0; mt < 2; mt++)
#pragma unroll
                for (int nt = 0; nt < 8; nt++) {
                    const int np = nt >> 1, hb = (nt & 1) << 1;
                    mma_bf16(acc[mt][nt], a[mt], b[np][hb], b[np][hb + 1]);
                }
        }
    };

    ldgA(0); ldgB(0); sts(A0_OFF, B0_OFF);
    __syncthreads();
    const int NC = K >> 5;
    for (int c = 0; c < NC; c++) {
        const int b = c & 1;
        if (c + 1 < NC) { ldgA(c + 1); ldgB(c + 1); }
        compute(b ? A1_OFF : A0_OFF, b ? B1_OFF : B0_OFF);
        if (c + 1 < NC) sts(b ? A0_OFF : A1_OFF, b ? B0_OFF : B1_OFF);
        __syncthreads();
    }

    // epilogue: bias + relu -> bf16, STG.32 (2 cols/thread)
#pragma unroll
    for (int mt = 0; mt < 2; mt++) {
        const int r0 = mBase + warp_m + mt * 16 + (lane >> 2);
#pragma unroll
        for (int nt = 0; nt < 8; nt++) {
            const int col = nBase + warp_n + nt * 8 + ((lane & 3) << 1);
            const float b0 = bias[col], b1 = bias[col + 1];
            if (r0 < M)
                *(uint32_t*)(C + (size_t)r0 * 256 + col) =
                    pack_bf16(fmaxf(acc[mt][nt][0] + b0, 0.f), fmaxf(acc[mt][nt][1] + b1, 0.f));
            if (r0 + 8 < M)
                *(uint32_t*)(C + (size_t)(r0 + 8) * 256 + col) =
                    pack_bf16(fmaxf(acc[mt][nt][2] + b0, 0.f), fmaxf(acc[mt][nt][3] + b1, 0.f));
        }
    }
}

// ---------------------------------------------------------------------------
// Edge GEMM (bf16 mma): A rows gathered [h[parent]|h[child]] (K=512),
// CRF masked fp32 output out[e*256 + r*16 + c].
// ---------------------------------------------------------------------------
__global__ __launch_bounds__(256) void hgemm_edge(
    const __nv_bfloat16* __restrict__ h, const __nv_bfloat16* __restrict__ Bt,
    const float* __restrict__ be,
    const int* __restrict__ parent, const int* __restrict__ child,
    const int* __restrict__ obs, const int* __restrict__ tl,
    float* __restrict__ out, int E)
{
    extern __shared__ uint8_t smem[];
    __shared__ int sPl[128], sCl[128], sOp[128], sOc[128];
    const uint32_t sbase = smem_u32(smem);
    const int tid = threadIdx.x, lane = tid & 31, wid = tid >> 5;
    const int mBase = blockIdx.y << 7, nBase = blockIdx.x << 7;
    const int warp_m = (wid & 3) << 5, warp_n = (wid >> 2) << 6;

    const int lr = tid >> 1;
    const int kh = (tid & 1) << 4;
    const int eA = mBase + lr;
    const bool ev = eA < E;
    const int pidx = ev ? parent[eA] : 0;
    const int cidx = ev ? child[eA] : 0;
    const __nv_bfloat16* pRow = h + (size_t)pidx * 256 + kh;
    const __nv_bfloat16* cRow = h + (size_t)cidx * 256 + kh;
    const __nv_bfloat16* bRow = Bt + (size_t)(nBase + lr) * 512 + kh;

    float acc[2][8][4];
#pragma unroll
    for (int i = 0; i < 2; i++)
#pragma unroll
        for (int j = 0; j < 8; j++)
#pragma unroll
            for (int l = 0; l < 4; l++) acc[i][j][l] = 0.f;

    uint32_t aR[8], bR[8];

    auto ldgA = [&](int c) {
        if (!ev) {
#pragma unroll
            for (int i = 0; i < 8; i++) aR[i] = 0;
            return;
        }
        const __nv_bfloat16* src = ((c < 8) ? pRow : cRow) + ((c & 7) << 5);
        const uint4* p = (const uint4*)src;
        uint4 v0 = p[0], v1 = p[1];
        aR[0] = v0.x; aR[1] = v0.y; aR[2] = v0.z; aR[3] = v0.w;
        aR[4] = v1.x; aR[5] = v1.y; aR[6] = v1.z; aR[7] = v1.w;
    };
    auto ldgB = [&](int c) {
        const uint4* p = (const uint4*)(bRow + c * 32);
        uint4 v0 = p[0], v1 = p[1];
        bR[0] = v0.x; bR[1] = v0.y; bR[2] = v0.z; bR[3] = v0.w;
        bR[4] = v1.x; bR[5] = v1.y; bR[6] = v1.z; bR[7] = v1.w;
    };
    auto sts = [&](uint32_t aOff, uint32_t bOff) {
        uint8_t* sa = smem + aOff + lr * RSTR + kh * 2;
        *(uint4*)(sa)      = make_uint4(aR[0], aR[1], aR[2], aR[3]);
        *(uint4*)(sa + 16) = make_uint4(aR[4], aR[5], aR[6], aR[7]);
        uint8_t* sb = smem + bOff + lr * RSTR + kh * 2;
        *(uint4*)(sb)      = make_uint4(bR[0], bR[1], bR[2], bR[3]);
        *(uint4*)(sb + 16) = make_uint4(bR[4], bR[5], bR[6], bR[7]);
    };
    auto compute = [&](uint32_t aOff, uint32_t bOff) {
        const uint32_t aBase = sbase + aOff + (warp_m + (lane & 15)) * RSTR + ((lane >> 4) << 4);
        const uint32_t bBase = sbase + bOff + ((lane & 7) + ((lane >> 4) << 3)) * RSTR + (((lane >> 3) & 1) << 4);
#pragma unroll
        for (int ks = 0; ks < 2; ks++) {
            uint32_t a[2][4];
            ldsm4(a[0][0], a[0][1], a[0][2], a[0][3], aBase + ks * 32);
            ldsm4(a[1][0], a[1][1], a[1][2], a[1][3], aBase + 16 * RSTR + ks * 32);
            uint32_t b[4][4];
#pragma unroll
            for (int np = 0; np < 4; np++)
                ldsm4(b[np][0], b[np][1], b[np][2], b[np][3], bBase + np * 16 * RSTR + ks * 32);
#pragma unroll
            for (int mt = 0; mt < 2; mt++)
#pragma unroll
                for (int nt = 0; nt < 8; nt++) {
                    const int np = nt >> 1, hb = (nt & 1) << 1;
                    mma_bf16(acc[mt][nt], a[mt], b[np][hb], b[np][hb + 1]);
                }
        }
    };

    ldgA(0); ldgB(0); sts(A0_OFF, B0_OFF);
    __syncthreads();
    const int NC = 16;
    for (int c = 0; c < NC; c++) {
        const int b = c & 1;
        if (c + 1 < NC) { ldgA(c + 1); ldgB(c + 1); }
        compute(b ? A1_OFF : A0_OFF, b ? B1_OFF : B0_OFF);
        if (c + 1 < NC) sts(b ? A0_OFF : A1_OFF, b ? B0_OFF : B1_OFF);
        __syncthreads();
    }

    // stage per-row CRF mask data
    if (tid < 128) {
        int e = mBase + tid;
        int pi = 0, ci = 0;
        if (e < E) { pi = parent[e]; ci = child[e]; }
        sPl[tid] = tl[pi]; sCl[tid] = tl[ci];
        sOp[tid] = obs[pi]; sOc[tid] = obs[ci];
    }
    __syncthreads();

    auto maskv = [&](float ep, int rloc, int rl, int cb) -> float {
        const int pl = sPl[rloc], cl = sCl[rloc];
        const int op = sOp[rloc], oc = sOc[rloc];
        if (op && oc) return (rl == pl && cb == cl) ? 0.f : AZf;
        if (oc)       return ep + ((rl == cl) ? 0.f : AZf);
        if (op)       return ep + ((cb == pl) ? 0.f : AZf);
        return ep;
    };

#pragma unroll
    for (int mt = 0; mt < 2; mt++) {
        const int rloc0 = warp_m + mt * 16 + (lane >> 2);
#pragma unroll
        for (int nt = 0; nt < 8; nt++) {
            const int col = nBase + warp_n + nt * 8 + ((lane & 3) << 1);
            const int rl = col >> 4, cb = col & 15;
            const int rl1 = (col + 1) >> 4, cb1 = (col + 1) & 15;
            const float b0 = be[col], b1 = be[col + 1];
            if (mBase + rloc0 < E) {
                float2 v;
                v.x = maskv(acc[mt][nt][0] + b0, rloc0, rl, cb);
                v.y = maskv(acc[mt][nt][1] + b1, rloc0, rl1, cb1);
                *(float2*)(out + (size_t)(mBase + rloc0) * 256 + col) = v;
            }
            if (mBase + rloc0 + 8 < E) {
                float2 v;
                v.x = maskv(acc[mt][nt][2] + b0, rloc0 + 8, rl, cb);
                v.y = maskv(acc[mt][nt][3] + b1, rloc0 + 8, rl1, cb1);
                *(float2*)(out + (size_t)(mBase + rloc0 + 8) * 256 + col) = v;
            }
        }
    }
}

// ---------------------------------------------------------------------------
// Unary: out[row,c] = obs ? (tl==c ? 0 : AZ) : h2[row]·Wu[:,c] + bu[c]
// ---------------------------------------------------------------------------
__global__ __launch_bounds__(256) void unary_kernel(
    const __nv_bfloat16* __restrict__ h, const float* __restrict__ Wu,
    const float* __restrict__ bu, const int* __restrict__ obs,
    const int* __restrict__ tl, float* __restrict__ out, int N)
{
    __shared__ float sW[256 * 16];
    __shared__ float sH[16][257];
    const int tid = threadIdx.x;
    for (int i = tid; i < 256 * 16; i += 256) sW[i] = Wu[i];
    const int row0 = blockIdx.x * 16;
    const int limit = (N - row0 < 16 ? N - row0 : 16) * 256;
    for (int i = tid; i < 16 * 256; i += 256)
        sH[i >> 8][i & 255] = (i < limit) ? __bfloat162float(h[(size_t)row0 * 256 + i]) : 0.f;
    __syncthreads();
    const int tx = tid & 15, ty = tid >> 4;
    const int row = row0 + ty;
    if (row >= N) return;
    float acc = 0.f;
#pragma unroll 8
    for (int k = 0; k < 256; k++) acc += sH[ty][k] * sW[k * 16 + tx];
    float v;
    if (obs[row]) v = (tl[row] == tx) ? 0.f : AZf;
    else          v = acc + bu[tx];
    out[(size_t)row * 16 + tx] = v;
}

// ---------------------------------------------------------------------------

extern "C" void kernel_launch(void* const* d_in, const int* in_sizes, int n_in,
                              void* d_out, int out_size)
{
    const float* features = (const float*)d_in[0];
    const int*   parent   = (const int*)  d_in[1];
    const int*   child    = (const int*)  d_in[2];
    const int*   obs      = (const int*)  d_in[3];
    const int*   tl       = (const int*)  d_in[4];
    const float* W1       = (const float*)d_in[5];
    const float* b1       = (const float*)d_in[6];
    const float* W2       = (const float*)d_in[7];
    const float* b2       = (const float*)d_in[8];
    const float* Wu       = (const float*)d_in[9];
    const float* bu       = (const float*)d_in[10];
    const float* We       = (const float*)d_in[11];
    const float* be       = (const float*)d_in[12];

    const int N = in_sizes[0] / 768;
    const int E = in_sizes[1];

    float* outU = (float*)d_out;
    float* outE = outU + (size_t)N * 16;

    __nv_bfloat16 *h1, *h2, *wt1, *wt2, *wet;
    cudaGetSymbolAddress((void**)&h1,  g_h1);
    cudaGetSymbolAddress((void**)&h2,  g_h2);
    cudaGetSymbolAddress((void**)&wt1, g_Wt1);
    cudaGetSymbolAddress((void**)&wt2, g_Wt2);
    cudaGetSymbolAddress((void**)&wet, g_Wet);

    transpose_w<<<dim3(8, 24), dim3(32, 8)>>>(W1, wt1, 768, 256);
    transpose_w<<<dim3(8, 8),  dim3(32, 8)>>>(W2, wt2, 256, 256);
    transpose_w<<<dim3(8, 16), dim3(32, 8)>>>(We, wet, 512, 256);

    const int gM = (N + 127) / 128;
    const int gE = (E + 127) / 128;

    hgemm_relu<false><<<dim3(2, gM), 256, SMEM_BYTES>>>(features, wt1, b1, h1, N, 768);
    hgemm_relu<true ><<<dim3(2, gM), 256, SMEM_BYTES>>>(h1,       wt2, b2, h2, N, 256);
    unary_kernel<<<(N + 15) / 16, 256>>>(h2, Wu, bu, obs, tl, outU, N);
    hgemm_edge<<<dim3(2, gE), 256, SMEM_BYTES>>>(h2, wet, be, parent, child, obs, tl, outE, E);
}